// round 14
// baseline (speedup 1.0000x reference)
#include <cuda_runtime.h>
#include <cuda_fp16.h>
#include <math.h>

// Problem constants: N=100000, E=1600000, D_IN=128, D_OUT=32, K=10
#define MAXN 100000
#define MAXE 1600000
#define DIN 128
#define DOUT 32
#define KHOPS 10
#define CAP 64            // per-node adjacency capacity (Poisson(16): P(>64) ~ 2e-18)
#define ROWB 64           // bytes per feature row (32 fp16)

// Scratch (static __device__ — no allocations allowed). +1 row = dummy zero row.
__device__ __half g_h [(MAXN + 1) * DOUT];   // h = xW+b            (fp16)
__device__ __half g_hd[(MAXN + 1) * DOUT];   // hd = dinv * h       (fp16)
__device__ __half g_z0[(MAXN + 1) * DOUT];   // z ping              (fp16)
__device__ __half g_z1[(MAXN + 1) * DOUT];   // z pong              (fp16)
__device__ float  g_dinv[MAXN];
__device__ float  g_d2[MAXN];                // dinv^2
__device__ int    g_cnt[MAXN];
__device__ int    g_eoff[MAXN * CAP];        // padded adjacency: BYTE offsets (src*64)
__device__ float  g_tk[KHOPS + 1];           // t / k
__device__ float  g_c0;                      // e^{-t}
__device__ int    g_is64;                    // 1 if edge_index buffer is int64

__device__ __forceinline__ __half2 u2h(unsigned u) { return *reinterpret_cast<__half2*>(&u); }
__device__ __forceinline__ unsigned h2u(__half2 h) { return *reinterpret_cast<unsigned*>(&h); }

// ---------------------------------------------------------------------------
__device__ __forceinline__ int edge_val(const void* ei_raw, long long idx) {
    if (g_is64) return (int)((const long long*)ei_raw)[idx];
    return ((const int*)ei_raw)[idx];
}

// zero counters + zero dummy rows + detect edge dtype + Horner coeffs (fused)
__global__ void k_setup(int n, const void* __restrict__ ei_raw,
                        const float* __restrict__ t_ptr) {
    int i = blockIdx.x * blockDim.x + threadIdx.x;
    if (i < n) g_cnt[i] = 0;
    if (blockIdx.x == 0 && threadIdx.x < DOUT) {
        g_z0[(size_t)MAXN * DOUT + threadIdx.x] = __float2half(0.f);
        g_z1[(size_t)MAXN * DOUT + threadIdx.x] = __float2half(0.f);
    }
    if (blockIdx.x == 0 && threadIdx.x == 0) {
        // Values in [0,1e5) < 2^31: true int64 has zero high words; an int32
        // buffer viewed as int64 packs the next index into the high word.
        const unsigned long long* p = (const unsigned long long*)ei_raw;
        int nonzero_hi = 0;
        for (int s = 0; s < 256; s++)
            if ((p[s] >> 32) != 0ull) nonzero_hi++;
        g_is64 = (nonzero_hi == 0) ? 1 : 0;

        double t = (double)(*t_ptr);
        g_c0 = (float)exp(-t);
        for (int k = 1; k <= KHOPS; k++) g_tk[k] = (float)(t / (double)k);
    }
}

// build padded adjacency: one atomicAdd per edge, store pre-scaled byte offset
__global__ void k_scatter(const void* __restrict__ ei, int e) {
    int i = blockIdx.x * blockDim.x + threadIdx.x;
    if (i < e) {
        int s = edge_val(ei, i);
        int d = edge_val(ei, (long long)e + i);
        int pos = atomicAdd(&g_cnt[d], 1);
        if (pos < CAP) g_eoff[d * CAP + pos] = s * ROWB;
    }
}

// h = x @ W + b; store h, hd = dinv*h, z_K = hd (fp16); dinv, dinv^2;
// pad adjacency rows up to a multiple of 16 with the dummy-row offset.
__global__ void __launch_bounds__(128) k_gemm(
        const float* __restrict__ x, const float* __restrict__ W,
        const float* __restrict__ b, int n) {
    __shared__ float Ws[DIN * DOUT];
    __shared__ float bs[DOUT];
    int tid = threadIdx.x;
    for (int i = tid; i < DIN * DOUT; i += blockDim.x) Ws[i] = W[i];
    if (tid < DOUT) bs[tid] = b[tid];
    __syncthreads();

    int warp = tid >> 5;
    int lane = tid & 31;
    int r0 = (blockIdx.x * 4 + warp) * 4;          // first of 4 rows
    if (r0 >= n) return;

    float acc0 = bs[lane], acc1 = bs[lane], acc2 = bs[lane], acc3 = bs[lane];
    const float* x0 = x + (size_t)r0 * DIN;
    bool h1 = r0 + 1 < n, h2 = r0 + 2 < n, h3 = r0 + 3 < n;

#pragma unroll 8
    for (int k4 = 0; k4 < DIN / 4; k4++) {
        float4 a0 = *(const float4*)(x0 + k4 * 4);
        float4 a1 = h1 ? *(const float4*)(x0 + DIN + k4 * 4) : make_float4(0, 0, 0, 0);
        float4 a2 = h2 ? *(const float4*)(x0 + 2 * DIN + k4 * 4) : make_float4(0, 0, 0, 0);
        float4 a3 = h3 ? *(const float4*)(x0 + 3 * DIN + k4 * 4) : make_float4(0, 0, 0, 0);
        float w0 = Ws[(k4 * 4 + 0) * DOUT + lane];
        float w1 = Ws[(k4 * 4 + 1) * DOUT + lane];
        float w2 = Ws[(k4 * 4 + 2) * DOUT + lane];
        float w3 = Ws[(k4 * 4 + 3) * DOUT + lane];
        acc0 = fmaf(a0.x, w0, acc0); acc0 = fmaf(a0.y, w1, acc0);
        acc0 = fmaf(a0.z, w2, acc0); acc0 = fmaf(a0.w, w3, acc0);
        acc1 = fmaf(a1.x, w0, acc1); acc1 = fmaf(a1.y, w1, acc1);
        acc1 = fmaf(a1.z, w2, acc1); acc1 = fmaf(a1.w, w3, acc1);
        acc2 = fmaf(a2.x, w0, acc2); acc2 = fmaf(a2.y, w1, acc2);
        acc2 = fmaf(a2.z, w2, acc2); acc2 = fmaf(a2.w, w3, acc2);
        acc3 = fmaf(a3.x, w0, acc3); acc3 = fmaf(a3.y, w1, acc3);
        acc3 = fmaf(a3.z, w2, acc3); acc3 = fmaf(a3.w, w3, acc3);
    }

#pragma unroll
    for (int r = 0; r < 4; r++) {
        int row = r0 + r;
        if (row >= n) break;
        float acc = (r == 0) ? acc0 : (r == 1) ? acc1 : (r == 2) ? acc2 : acc3;
        int truec = g_cnt[row];
        int cntc = truec > CAP ? CAP : truec;
        float di = rsqrtf((float)(truec + 1));
        if (lane == 0) { g_dinv[row] = di; g_d2[row] = di * di; }
        // pad adjacency to multiple of 16 with dummy zero-row offset
        int pad16 = (cntc + 15) & ~15;
        if (lane < pad16 - cntc) g_eoff[row * CAP + cntc + lane] = MAXN * ROWB;
        size_t idx = (size_t)row * DOUT + lane;
        __half hv  = __float2half_rn(acc);
        __half hdv = __float2half_rn(di * acc);
        g_h [idx] = hv;
        g_hd[idx] = hdv;
        g_z0[idx] = hdv;          // z_K = dinv * h
    }
}

// One Horner step in z-space. TWO nodes per warp:
//   node = warp*2 + (lane>>4), q = (lane>>2)&3 edge slot, fp = lane&3 (16B chunk).
//   4 lanes x LDG.128 cover one 64B row -> each gather instruction fetches 8 edges.
//   Critical-path ordering: iter-0 offsets (always-valid padded slots) and the
//   speculative iter-1 offsets are loaded in PARALLEL with g_cnt; the iter-1
//   gathers are guarded by cnt>16, whose predicate is ready when cnt lands.
//   fp16 reduce-scatter across q slots; all-lane branch-free epilogue.
//   S[d] = sum_adj z[s] + z[d];  k>1: z' = hd + (t/k) d^2 S;  k==1: out = e^{-t}(h + t dinv S)
__global__ void __launch_bounds__(256, 7) k_hop(float* __restrict__ out, int k,
                                                int n, int flip) {
    const __half* __restrict__ cur = flip ? g_z1 : g_z0;
    __half* __restrict__ nxt       = flip ? g_z0 : g_z1;

    int warp = (blockIdx.x * blockDim.x + threadIdx.x) >> 5;
    int lane = threadIdx.x & 31;
    int node = warp * 2 + (lane >> 4);
    if (node >= n) node = n - 1;           // dup work on tail; identical values, benign
    int q  = (lane >> 2) & 3;
    int fp = lane & 3;
    int hi = fp * 4 + q;                   // half2 component this lane will own

    const int4* offs4 = (const int4*)(g_eoff + node * CAP);
    const char* curb  = (const char*)cur + fp * 16;

    // --- independent loads issued back-to-back: o0, o1 (speculative), cnt ---
    int4 o0 = offs4[q];                    // slots 0..15: always initialized
    int4 o1 = offs4[4 + q];                // slots 16..31: valid only if cnt > 16
    int cnt = g_cnt[node];
    if (cnt > CAP) cnt = CAP;

    __half2 a0, a1, a2, a3;
    {   // iteration 0 (unconditional)
        uint4 r0 = *(const uint4*)(curb + o0.x);
        uint4 r1 = *(const uint4*)(curb + o0.y);
        uint4 r2 = *(const uint4*)(curb + o0.z);
        uint4 r3 = *(const uint4*)(curb + o0.w);
        a0 = __hadd2(__hadd2(u2h(r0.x), u2h(r1.x)), __hadd2(u2h(r2.x), u2h(r3.x)));
        a1 = __hadd2(__hadd2(u2h(r0.y), u2h(r1.y)), __hadd2(u2h(r2.y), u2h(r3.y)));
        a2 = __hadd2(__hadd2(u2h(r0.z), u2h(r1.z)), __hadd2(u2h(r2.z), u2h(r3.z)));
        a3 = __hadd2(__hadd2(u2h(r0.w), u2h(r1.w)), __hadd2(u2h(r2.w), u2h(r3.w)));
    }
    if (cnt > 16) {   // iteration 1 (offsets already in flight)
        uint4 r0 = *(const uint4*)(curb + o1.x);
        uint4 r1 = *(const uint4*)(curb + o1.y);
        uint4 r2 = *(const uint4*)(curb + o1.z);
        uint4 r3 = *(const uint4*)(curb + o1.w);
        a0 = __hadd2(a0, __hadd2(__hadd2(u2h(r0.x), u2h(r1.x)), __hadd2(u2h(r2.x), u2h(r3.x))));
        a1 = __hadd2(a1, __hadd2(__hadd2(u2h(r0.y), u2h(r1.y)), __hadd2(u2h(r2.y), u2h(r3.y))));
        a2 = __hadd2(a2, __hadd2(__hadd2(u2h(r0.z), u2h(r1.z)), __hadd2(u2h(r2.z), u2h(r3.z))));
        a3 = __hadd2(a3, __hadd2(__hadd2(u2h(r0.w), u2h(r1.w)), __hadd2(u2h(r2.w), u2h(r3.w))));
    }
    // rare tail: deg > 32 (P ~ 1e-4 per node)
    int pad = (cnt + 15) & ~15;
    for (int base = 32; base < pad; base += 16) {
        int4 o = offs4[(base >> 2) + q];
        uint4 r0 = *(const uint4*)(curb + o.x);
        uint4 r1 = *(const uint4*)(curb + o.y);
        uint4 r2 = *(const uint4*)(curb + o.z);
        uint4 r3 = *(const uint4*)(curb + o.w);
        a0 = __hadd2(a0, __hadd2(__hadd2(u2h(r0.x), u2h(r1.x)), __hadd2(u2h(r2.x), u2h(r3.x))));
        a1 = __hadd2(a1, __hadd2(__hadd2(u2h(r0.y), u2h(r1.y)), __hadd2(u2h(r2.y), u2h(r3.y))));
        a2 = __hadd2(a2, __hadd2(__hadd2(u2h(r0.z), u2h(r1.z)), __hadd2(u2h(r2.z), u2h(r3.z))));
        a3 = __hadd2(a3, __hadd2(__hadd2(u2h(r0.w), u2h(r1.w)), __hadd2(u2h(r2.w), u2h(r3.w))));
    }

    // ---- epilogue loads hoisted: overlap the shfl chain below ----
    const __half2* currow = (const __half2*)((const char*)cur + (size_t)node * ROWB);
    __half2 selfv = currow[hi];                                   // 16 lanes -> 64B line
    const char* hb = (k > 1) ? (const char*)g_hd : (const char*)g_h;
    __half2 hv = ((const __half2*)(hb + (size_t)node * ROWB))[hi];
    float c  = (k > 1) ? (g_tk[k] * g_d2[node]) : (g_tk[1] * g_dinv[node]);

    // ---- fp16 reduce-scatter across the 4 q slots (lane bits 2,3) ----
    int p0 = q & 1;
    __half2 rx = u2h(__shfl_xor_sync(0xffffffffu, h2u(p0 ? a0 : a1), 4));
    __half2 ry = u2h(__shfl_xor_sync(0xffffffffu, h2u(p0 ? a2 : a3), 4));
    __half2 u  = __hadd2(p0 ? a1 : a0, rx);   // component p0
    __half2 v  = __hadd2(p0 ? a3 : a2, ry);   // component p0 + 2
    int p1 = (q >> 1) & 1;
    __half2 rz = u2h(__shfl_xor_sync(0xffffffffu, h2u(p1 ? u : v), 8));
    __half2 S16 = __hadd2(p1 ? v : u, rz);    // complete sum, component hi = fp*4+q

    // ---- branch-free epilogue on all lanes ----
    float2 S  = __half22float2(S16);
    float2 sf = __half22float2(selfv);
    float2 hf = __half22float2(hv);
    S.x += sf.x;  S.y += sf.y;                // self-loop term in fp32

    if (k > 1) {
        __half2 w = __floats2half2_rn(fmaf(c, S.x, hf.x), fmaf(c, S.y, hf.y));
        ((__half2*)((char*)nxt + (size_t)node * ROWB))[hi] = w;
    } else {
        float c0 = g_c0;
        float2 w = make_float2(c0 * fmaf(c, S.x, hf.x), c0 * fmaf(c, S.y, hf.y));
        *(float2*)(out + (size_t)node * DOUT + hi * 2) = w;
    }
}

// ---------------------------------------------------------------------------
extern "C" void kernel_launch(void* const* d_in, const int* in_sizes, int n_in,
                              void* d_out, int out_size) {
    const float* x  = (const float*)d_in[0];
    const void*  ei = d_in[1];              // int32 or int64, detected on device
    const float* W  = (const float*)d_in[2];
    const float* b  = (const float*)d_in[3];
    const float* t  = (const float*)d_in[4];
    float* out = (float*)d_out;

    int n = in_sizes[0] / DIN;   // 100000
    int e = in_sizes[1] / 2;     // 1600000

    const int T = 256;
    int gn  = (n + T - 1) / T;
    int ge  = (e + T - 1) / T;
    int gg  = (n + 15) / 16;                     // gemm: 16 rows per 128-thread block
    int gh  = (n + 15) / 16;                     // hop: 8 warps x 2 nodes per block

    // Build (3 kernels; graph-captured, no allocations, no syncs)
    k_setup<<<gn, T>>>(n, ei, t);
    k_scatter<<<ge, T>>>(ei, e);
    k_gemm<<<gg, 128>>>(x, W, b, n);

    // Horner in z-space: z <- hd + (t/k) d^2 ((A+I) z), k = K..2;
    // k = 1 writes out = e^{-t} (h + t dinv (A+I) z)
    int flip = 0;
    for (int k = KHOPS; k >= 1; k--) {
        k_hop<<<gh, T>>>(out, k, n, flip);
        flip ^= 1;
    }
}

// round 15
// speedup vs baseline: 1.0121x; 1.0121x over previous
#include <cuda_runtime.h>
#include <cuda_fp16.h>
#include <math.h>

// Problem constants: N=100000, E=1600000, D_IN=128, D_OUT=32, K=10
#define MAXN 100000
#define MAXE 1600000
#define DIN 128
#define DOUT 32
#define KHOPS 10
#define CAP 64            // per-node adjacency capacity (Poisson(16): P(>64) ~ 2e-18)
#define ROWB 64           // bytes per feature row (32 fp16)

// Scratch (static __device__ — no allocations allowed). +1 row = dummy zero row.
__device__ __half g_h [(MAXN + 1) * DOUT];   // h = xW+b            (fp16)
__device__ __half g_hd[(MAXN + 1) * DOUT];   // hd = dinv * h       (fp16)
__device__ __half g_z0[(MAXN + 1) * DOUT];   // z ping              (fp16)
__device__ __half g_z1[(MAXN + 1) * DOUT];   // z pong              (fp16)
__device__ float  g_dinv[MAXN];
__device__ float  g_d2[MAXN];                // dinv^2
__device__ int    g_cnt[MAXN];
__device__ int    g_eoff[MAXN * CAP];        // padded adjacency: BYTE offsets (src*64)
__device__ float  g_tk[KHOPS + 1];           // t / k
__device__ float  g_c0;                      // e^{-t}
__device__ int    g_is64;                    // 1 if edge_index buffer is int64

__device__ __forceinline__ __half2 u2h(unsigned u) { return *reinterpret_cast<__half2*>(&u); }
__device__ __forceinline__ unsigned h2u(__half2 h) { return *reinterpret_cast<unsigned*>(&h); }

// ---------------------------------------------------------------------------
__device__ __forceinline__ int edge_val(const void* ei_raw, long long idx) {
    if (g_is64) return (int)((const long long*)ei_raw)[idx];
    return ((const int*)ei_raw)[idx];
}

// zero counters + zero dummy rows + detect edge dtype + Horner coeffs (fused)
__global__ void k_setup(int n, const void* __restrict__ ei_raw,
                        const float* __restrict__ t_ptr) {
    int i = blockIdx.x * blockDim.x + threadIdx.x;
    if (i < n) g_cnt[i] = 0;
    if (blockIdx.x == 0 && threadIdx.x < DOUT) {
        g_z0[(size_t)MAXN * DOUT + threadIdx.x] = __float2half(0.f);
        g_z1[(size_t)MAXN * DOUT + threadIdx.x] = __float2half(0.f);
    }
    if (blockIdx.x == 0 && threadIdx.x == 0) {
        // Values in [0,1e5) < 2^31: true int64 has zero high words; an int32
        // buffer viewed as int64 packs the next index into the high word.
        const unsigned long long* p = (const unsigned long long*)ei_raw;
        int nonzero_hi = 0;
        for (int s = 0; s < 256; s++)
            if ((p[s] >> 32) != 0ull) nonzero_hi++;
        g_is64 = (nonzero_hi == 0) ? 1 : 0;

        double t = (double)(*t_ptr);
        g_c0 = (float)exp(-t);
        for (int k = 1; k <= KHOPS; k++) g_tk[k] = (float)(t / (double)k);
    }
}

// build padded adjacency: one atomicAdd per edge, store pre-scaled byte offset
__global__ void k_scatter(const void* __restrict__ ei, int e) {
    int i = blockIdx.x * blockDim.x + threadIdx.x;
    if (i < e) {
        int s = edge_val(ei, i);
        int d = edge_val(ei, (long long)e + i);
        int pos = atomicAdd(&g_cnt[d], 1);
        if (pos < CAP) g_eoff[d * CAP + pos] = s * ROWB;
    }
}

// h = x @ W + b; store h, hd = dinv*h, z_K = hd (fp16); dinv, dinv^2;
// pad adjacency rows up to a multiple of 16 with the dummy-row offset.
__global__ void __launch_bounds__(128) k_gemm(
        const float* __restrict__ x, const float* __restrict__ W,
        const float* __restrict__ b, int n) {
    __shared__ float Ws[DIN * DOUT];
    __shared__ float bs[DOUT];
    int tid = threadIdx.x;
    for (int i = tid; i < DIN * DOUT; i += blockDim.x) Ws[i] = W[i];
    if (tid < DOUT) bs[tid] = b[tid];
    __syncthreads();

    int warp = tid >> 5;
    int lane = tid & 31;
    int r0 = (blockIdx.x * 4 + warp) * 4;          // first of 4 rows
    if (r0 >= n) return;

    float acc0 = bs[lane], acc1 = bs[lane], acc2 = bs[lane], acc3 = bs[lane];
    const float* x0 = x + (size_t)r0 * DIN;
    bool h1 = r0 + 1 < n, h2 = r0 + 2 < n, h3 = r0 + 3 < n;

#pragma unroll 8
    for (int k4 = 0; k4 < DIN / 4; k4++) {
        float4 a0 = *(const float4*)(x0 + k4 * 4);
        float4 a1 = h1 ? *(const float4*)(x0 + DIN + k4 * 4) : make_float4(0, 0, 0, 0);
        float4 a2 = h2 ? *(const float4*)(x0 + 2 * DIN + k4 * 4) : make_float4(0, 0, 0, 0);
        float4 a3 = h3 ? *(const float4*)(x0 + 3 * DIN + k4 * 4) : make_float4(0, 0, 0, 0);
        float w0 = Ws[(k4 * 4 + 0) * DOUT + lane];
        float w1 = Ws[(k4 * 4 + 1) * DOUT + lane];
        float w2 = Ws[(k4 * 4 + 2) * DOUT + lane];
        float w3 = Ws[(k4 * 4 + 3) * DOUT + lane];
        acc0 = fmaf(a0.x, w0, acc0); acc0 = fmaf(a0.y, w1, acc0);
        acc0 = fmaf(a0.z, w2, acc0); acc0 = fmaf(a0.w, w3, acc0);
        acc1 = fmaf(a1.x, w0, acc1); acc1 = fmaf(a1.y, w1, acc1);
        acc1 = fmaf(a1.z, w2, acc1); acc1 = fmaf(a1.w, w3, acc1);
        acc2 = fmaf(a2.x, w0, acc2); acc2 = fmaf(a2.y, w1, acc2);
        acc2 = fmaf(a2.z, w2, acc2); acc2 = fmaf(a2.w, w3, acc2);
        acc3 = fmaf(a3.x, w0, acc3); acc3 = fmaf(a3.y, w1, acc3);
        acc3 = fmaf(a3.z, w2, acc3); acc3 = fmaf(a3.w, w3, acc3);
    }

#pragma unroll
    for (int r = 0; r < 4; r++) {
        int row = r0 + r;
        if (row >= n) break;
        float acc = (r == 0) ? acc0 : (r == 1) ? acc1 : (r == 2) ? acc2 : acc3;
        int truec = g_cnt[row];
        int cntc = truec > CAP ? CAP : truec;
        float di = rsqrtf((float)(truec + 1));
        if (lane == 0) { g_dinv[row] = di; g_d2[row] = di * di; }
        // pad adjacency to multiple of 16 with dummy zero-row offset
        int pad16 = (cntc + 15) & ~15;
        if (lane < pad16 - cntc) g_eoff[row * CAP + cntc + lane] = MAXN * ROWB;
        size_t idx = (size_t)row * DOUT + lane;
        __half hv  = __float2half_rn(acc);
        __half hdv = __float2half_rn(di * acc);
        g_h [idx] = hv;
        g_hd[idx] = hdv;
        g_z0[idx] = hdv;          // z_K = dinv * h
    }
}

// One Horner step in z-space. TWO nodes per warp:
//   node = warp*2 + (lane>>4), q = (lane>>2)&3 edge slot, fp = lane&3 (16B chunk).
//   4 lanes x LDG.128 cover one 64B row -> each gather instruction fetches 8 edges.
//   Critical-path ordering: iter-0 offsets (always-valid padded slots) and the
//   speculative iter-1 offsets are loaded in PARALLEL with g_cnt; the iter-1
//   gathers are guarded by cnt>16, whose predicate is ready when cnt lands.
//   fp16 reduce-scatter across q slots; all-lane branch-free epilogue.
//   S[d] = sum_adj z[s] + z[d];  k>1: z' = hd + (t/k) d^2 S;  k==1: out = e^{-t}(h + t dinv S)
__global__ void __launch_bounds__(256, 7) k_hop(float* __restrict__ out, int k,
                                                int n, int flip) {
    const __half* __restrict__ cur = flip ? g_z1 : g_z0;
    __half* __restrict__ nxt       = flip ? g_z0 : g_z1;

    int warp = (blockIdx.x * blockDim.x + threadIdx.x) >> 5;
    int lane = threadIdx.x & 31;
    int node = warp * 2 + (lane >> 4);
    if (node >= n) node = n - 1;           // dup work on tail; identical values, benign
    int q  = (lane >> 2) & 3;
    int fp = lane & 3;
    int hi = fp * 4 + q;                   // half2 component this lane will own

    const int4* offs4 = (const int4*)(g_eoff + node * CAP);
    const char* curb  = (const char*)cur + fp * 16;

    // --- independent loads issued back-to-back: o0, o1 (speculative), cnt ---
    int4 o0 = offs4[q];                    // slots 0..15: always initialized
    int4 o1 = offs4[4 + q];                // slots 16..31: valid only if cnt > 16
    int cnt = g_cnt[node];
    if (cnt > CAP) cnt = CAP;

    __half2 a0, a1, a2, a3;
    {   // iteration 0 (unconditional)
        uint4 r0 = *(const uint4*)(curb + o0.x);
        uint4 r1 = *(const uint4*)(curb + o0.y);
        uint4 r2 = *(const uint4*)(curb + o0.z);
        uint4 r3 = *(const uint4*)(curb + o0.w);
        a0 = __hadd2(__hadd2(u2h(r0.x), u2h(r1.x)), __hadd2(u2h(r2.x), u2h(r3.x)));
        a1 = __hadd2(__hadd2(u2h(r0.y), u2h(r1.y)), __hadd2(u2h(r2.y), u2h(r3.y)));
        a2 = __hadd2(__hadd2(u2h(r0.z), u2h(r1.z)), __hadd2(u2h(r2.z), u2h(r3.z)));
        a3 = __hadd2(__hadd2(u2h(r0.w), u2h(r1.w)), __hadd2(u2h(r2.w), u2h(r3.w)));
    }
    if (cnt > 16) {   // iteration 1 (offsets already in flight)
        uint4 r0 = *(const uint4*)(curb + o1.x);
        uint4 r1 = *(const uint4*)(curb + o1.y);
        uint4 r2 = *(const uint4*)(curb + o1.z);
        uint4 r3 = *(const uint4*)(curb + o1.w);
        a0 = __hadd2(a0, __hadd2(__hadd2(u2h(r0.x), u2h(r1.x)), __hadd2(u2h(r2.x), u2h(r3.x))));
        a1 = __hadd2(a1, __hadd2(__hadd2(u2h(r0.y), u2h(r1.y)), __hadd2(u2h(r2.y), u2h(r3.y))));
        a2 = __hadd2(a2, __hadd2(__hadd2(u2h(r0.z), u2h(r1.z)), __hadd2(u2h(r2.z), u2h(r3.z))));
        a3 = __hadd2(a3, __hadd2(__hadd2(u2h(r0.w), u2h(r1.w)), __hadd2(u2h(r2.w), u2h(r3.w))));
    }
    // rare tail: deg > 32 (P ~ 1e-4 per node)
    int pad = (cnt + 15) & ~15;
    for (int base = 32; base < pad; base += 16) {
        int4 o = offs4[(base >> 2) + q];
        uint4 r0 = *(const uint4*)(curb + o.x);
        uint4 r1 = *(const uint4*)(curb + o.y);
        uint4 r2 = *(const uint4*)(curb + o.z);
        uint4 r3 = *(const uint4*)(curb + o.w);
        a0 = __hadd2(a0, __hadd2(__hadd2(u2h(r0.x), u2h(r1.x)), __hadd2(u2h(r2.x), u2h(r3.x))));
        a1 = __hadd2(a1, __hadd2(__hadd2(u2h(r0.y), u2h(r1.y)), __hadd2(u2h(r2.y), u2h(r3.y))));
        a2 = __hadd2(a2, __hadd2(__hadd2(u2h(r0.z), u2h(r1.z)), __hadd2(u2h(r2.z), u2h(r3.z))));
        a3 = __hadd2(a3, __hadd2(__hadd2(u2h(r0.w), u2h(r1.w)), __hadd2(u2h(r2.w), u2h(r3.w))));
    }

    // ---- epilogue loads hoisted: overlap the shfl chain below ----
    const __half2* currow = (const __half2*)((const char*)cur + (size_t)node * ROWB);
    __half2 selfv = currow[hi];                                   // 16 lanes -> 64B line
    const char* hb = (k > 1) ? (const char*)g_hd : (const char*)g_h;
    __half2 hv = ((const __half2*)(hb + (size_t)node * ROWB))[hi];
    float c  = (k > 1) ? (g_tk[k] * g_d2[node]) : (g_tk[1] * g_dinv[node]);

    // ---- fp16 reduce-scatter across the 4 q slots (lane bits 2,3) ----
    int p0 = q & 1;
    __half2 rx = u2h(__shfl_xor_sync(0xffffffffu, h2u(p0 ? a0 : a1), 4));
    __half2 ry = u2h(__shfl_xor_sync(0xffffffffu, h2u(p0 ? a2 : a3), 4));
    __half2 u  = __hadd2(p0 ? a1 : a0, rx);   // component p0
    __half2 v  = __hadd2(p0 ? a3 : a2, ry);   // component p0 + 2
    int p1 = (q >> 1) & 1;
    __half2 rz = u2h(__shfl_xor_sync(0xffffffffu, h2u(p1 ? u : v), 8));
    __half2 S16 = __hadd2(p1 ? v : u, rz);    // complete sum, component hi = fp*4+q

    // ---- branch-free epilogue on all lanes ----
    float2 S  = __half22float2(S16);
    float2 sf = __half22float2(selfv);
    float2 hf = __half22float2(hv);
    S.x += sf.x;  S.y += sf.y;                // self-loop term in fp32

    if (k > 1) {
        __half2 w = __floats2half2_rn(fmaf(c, S.x, hf.x), fmaf(c, S.y, hf.y));
        ((__half2*)((char*)nxt + (size_t)node * ROWB))[hi] = w;
    } else {
        float c0 = g_c0;
        float2 w = make_float2(c0 * fmaf(c, S.x, hf.x), c0 * fmaf(c, S.y, hf.y));
        *(float2*)(out + (size_t)node * DOUT + hi * 2) = w;
    }
}

// ---------------------------------------------------------------------------
extern "C" void kernel_launch(void* const* d_in, const int* in_sizes, int n_in,
                              void* d_out, int out_size) {
    const float* x  = (const float*)d_in[0];
    const void*  ei = d_in[1];              // int32 or int64, detected on device
    const float* W  = (const float*)d_in[2];
    const float* b  = (const float*)d_in[3];
    const float* t  = (const float*)d_in[4];
    float* out = (float*)d_out;

    int n = in_sizes[0] / DIN;   // 100000
    int e = in_sizes[1] / 2;     // 1600000

    const int T = 256;
    int gn  = (n + T - 1) / T;
    int ge  = (e + T - 1) / T;
    int gg  = (n + 15) / 16;                     // gemm: 16 rows per 128-thread block
    int gh  = (n + 15) / 16;                     // hop: 8 warps x 2 nodes per block

    // Build (3 kernels; graph-captured, no allocations, no syncs)
    k_setup<<<gn, T>>>(n, ei, t);
    k_scatter<<<ge, T>>>(ei, e);
    k_gemm<<<gg, 128>>>(x, W, b, n);

    // Horner in z-space: z <- hd + (t/k) d^2 ((A+I) z), k = K..2;
    // k = 1 writes out = e^{-t} (h + t dinv (A+I) z)
    int flip = 0;
    for (int k = KHOPS; k >= 1; k--) {
        k_hop<<<gh, T>>>(out, k, n, flip);
        flip ^= 1;
    }
}